// round 16
// baseline (speedup 1.0000x reference)
#include <cuda_runtime.h>
#include <cstdint>

typedef unsigned long long u64;
#define DEV static __device__ __forceinline__

static constexpr int L_ = 3;
static constexpr int NB = 128;   // 128 CTAs, 8 rows each
static constexpr int NT = 512;   // 16 warps

// ---------------- device globals ----------------
__device__ float g_P[2][1024 * 128];   // double-buffered Pj
__device__ float g_Wc[L_][128 * 128];  // ew2 @ nw1b
__device__ float g_cb[L_][128];        // eb2 @ nw1b
__device__ unsigned g_bar[4];          // monotonic barrier counters (replay-safe)

// ---------------- f32x2 helpers (agg path) ----------------
DEV u64 pk(float lo, float hi) {
    u64 r; asm("mov.b64 %0,{%1,%2};" : "=l"(r) : "f"(lo), "f"(hi)); return r;
}
DEV void upk(u64 v, float& lo, float& hi) {
    asm("mov.b64 {%0,%1},%2;" : "=f"(lo), "=f"(hi) : "l"(v));
}
DEV u64 add2(u64 a, u64 b) {
    u64 r; asm("add.rn.f32x2 %0,%1,%2;" : "=l"(r) : "l"(a), "l"(b)); return r;
}
DEV u64 fma2(u64 a, u64 b, u64 c) {
    u64 r; asm("fma.rn.f32x2 %0,%1,%2,%3;" : "=l"(r) : "l"(a), "l"(b), "l"(c)); return r;
}
DEV u64 relu2(u64 v) {
    float lo, hi; upk(v, lo, hi);
    return pk(fmaxf(lo, 0.f), fmaxf(hi, 0.f));
}

// ---------------- tf32 mma helpers ----------------
DEV unsigned tf32r(float v) {
    unsigned r; asm("cvt.rna.tf32.f32 %0, %1;" : "=r"(r) : "f"(v)); return r;
}
DEV void mma8(float d[4], unsigned a0, unsigned a1, unsigned a2, unsigned a3,
              unsigned b0, unsigned b1) {
    asm volatile(
        "mma.sync.aligned.m16n8k8.row.col.f32.tf32.tf32.f32 "
        "{%0,%1,%2,%3}, {%4,%5,%6,%7}, {%8,%9}, {%0,%1,%2,%3};"
        : "+f"(d[0]), "+f"(d[1]), "+f"(d[2]), "+f"(d[3])
        : "r"(a0), "r"(a1), "r"(a2), "r"(a3), "r"(b0), "r"(b1));
}

// ---------------- split grid barrier (monotonic counters; replay-safe) ----------------
DEV unsigned ld_acq(const unsigned* p) {
    unsigned v;
    asm volatile("ld.acquire.gpu.global.u32 %0,[%1];" : "=r"(v) : "l"(p) : "memory");
    return v;
}
DEV void bar_arrive(int bidx, int tid, unsigned* sT) {
    __syncthreads();
    if (tid == 0) {
        __threadfence();
        unsigned t = atomicAdd(&g_bar[bidx], 1u);
        *sT = (t / (unsigned)NB + 1u) * (unsigned)NB;
    }
}
DEV void bar_wait(int bidx, int tid, unsigned* sT) {
    __syncthreads();
    if (tid == 0) {
        unsigned target = *sT;
        while (ld_acq(&g_bar[bidx]) < target) { __nanosleep(64); }
        __threadfence();
    }
    __syncthreads();
}

// ---------------- tensor-core GEMM: out[8 x 128] = A[8 x 128] @ W[128 x 128] ------
// A in smem, row stride 132 (conflict-free for fragment pattern); W global via __ldg.
// warp w owns cols [w*8, w*8+8); full K in register accumulators d[4] (d0,d1 valid:
// row = lane>>2, cols = c0 + 2*(lane&3) .. +1). M rows 8..15 are junk (a1,a3 = a0,a2).
DEV void gemm_t(const float* __restrict__ sA, const float* __restrict__ W,
                int g, int tg, int c0, float d[4]) {
    const float* ap = sA + g * 132 + tg;
    const float* wp = W + tg * 128 + c0 + g;
#pragma unroll
    for (int ks = 0; ks < 16; ks++) {
        unsigned a0 = tf32r(ap[ks * 8]);
        unsigned a2 = tf32r(ap[ks * 8 + 4]);
        unsigned b0 = tf32r(__ldg(wp + ks * 1024));
        unsigned b1 = tf32r(__ldg(wp + ks * 1024 + 512));
        mma8(d, a0, a0, a2, a2, b0, b1);
    }
}

// u64 pair-reduce over 8 partials (stride 1024 floats); f0 = even float offset
DEV u64 reduce8_2(const float* __restrict__ sPart, int f0) {
    u64 p0 = *(const u64*)(sPart + f0);
    u64 p1 = *(const u64*)(sPart + f0 + 1024);
    u64 p2 = *(const u64*)(sPart + f0 + 2048);
    u64 p3 = *(const u64*)(sPart + f0 + 3072);
    u64 p4 = *(const u64*)(sPart + f0 + 4096);
    u64 p5 = *(const u64*)(sPart + f0 + 5120);
    u64 p6 = *(const u64*)(sPart + f0 + 6144);
    u64 p7 = *(const u64*)(sPart + f0 + 7168);
    return add2(add2(add2(p0, p1), add2(p2, p3)), add2(add2(p4, p5), add2(p6, p7)));
}

// ---------------- agg (R14 form): warp=(ig2,jq8), 4i x 4d, 32 j; Pj via LDG.cg ----
DEV void agg_ldg(const float* __restrict__ Pjb, const float* __restrict__ sAdj2,
                 const u64 xi[4][2], u64 acc[4][2], int lane, int ig, int jq) {
    const float* pj = Pjb + jq * 32 * 128 + lane * 4;
    const float* ad = sAdj2 + jq * 32 * 16 + ig * 8;
#pragma unroll 8
    for (int jj = 0; jj < 32; jj++) {
        ulonglong2 xj = __ldcg((const ulonglong2*)(pj + jj * 128));
        ulonglong2 a01 = *(const ulonglong2*)(ad + jj * 16);
        ulonglong2 a23 = *(const ulonglong2*)(ad + jj * 16 + 4);
        u64 t;
        t = relu2(add2(xi[0][0], xj.x)); acc[0][0] = fma2(t, a01.x, acc[0][0]);
        t = relu2(add2(xi[0][1], xj.y)); acc[0][1] = fma2(t, a01.x, acc[0][1]);
        t = relu2(add2(xi[1][0], xj.x)); acc[1][0] = fma2(t, a01.y, acc[1][0]);
        t = relu2(add2(xi[1][1], xj.y)); acc[1][1] = fma2(t, a01.y, acc[1][1]);
        t = relu2(add2(xi[2][0], xj.x)); acc[2][0] = fma2(t, a23.x, acc[2][0]);
        t = relu2(add2(xi[2][1], xj.y)); acc[2][1] = fma2(t, a23.x, acc[2][1]);
        t = relu2(add2(xi[3][0], xj.x)); acc[3][0] = fma2(t, a23.y, acc[3][0]);
        t = relu2(add2(xi[3][1], xj.y)); acc[3][1] = fma2(t, a23.y, acc[3][1]);
    }
}

// ---------------- smem layout (floats) ----------------
// sPart 0 (8192) | sATs 8192 (1056) | sNTs 9248 (1056) | sPi 10304 (1056)
// sPn 11360 (1056) | sAdj2 12416 (4096) | s_rs 16512 (8) | sX 16520 (1024)
// sBarT 17544 (1)
static constexpr int SMEM_FLOATS = 17548;   // 70192 B

__global__ void __launch_bounds__(NT, 1) k_main(
    float* __restrict__ x, const float* __restrict__ nf, const float* __restrict__ adj,
    const float* __restrict__ ew1, const float* __restrict__ eb1,
    const float* __restrict__ ew2, const float* __restrict__ eb2,
    const float* __restrict__ nw1, const float* __restrict__ nb1,
    const float* __restrict__ nw2, const float* __restrict__ nb2) {
    extern __shared__ float sm[];
    float* sPart = sm;
    float* sATs = sm + 8192;    // [8][132]
    float* sNTs = sm + 9248;    // [8][132]
    float* sPi = sm + 10304;    // [8][132]
    float* sPn = sm + 11360;    // [8][132]
    float* sAdj2 = sm + 12416;  // [256 j][16] dup'd pairs
    float* s_rs = sm + 16512;
    float* sX = sm + 16520;     // [1024] linear
    unsigned* sBarT = (unsigned*)(sm + 17544);

    int tid = threadIdx.x, lane = tid & 31, w = tid >> 5;
    int rb = blockIdx.x;        // rows rb*8 .. rb*8+7
    int b = rb >> 5;            // batch
    int il0 = (rb & 31) * 8;    // local i base in batch
    int g = lane >> 2, tg = lane & 3, c0 = w * 8;   // mma fragment roles
    int col = c0 + 2 * tg;                          // epilogue col pair
    int f0x = g * 128 + col;                        // linear x index of pair
    int ig = w & 1, jq = w >> 1;                    // agg roles
    int pf0 = 2 * tid;                              // reduce pair offset
    int pr = pf0 >> 7, pcc = pf0 & 127;

    // ================= setup: produce Wc/cb, arrive, local setup, wait ==========
    if (rb < 48) {   // Wc[l] rows r8*8..+7 = ew2[l] @ nw1b[l]
        int l = rb / 16, r8 = rb % 16;
#pragma unroll
        for (int q = 0; q < 2; q++) {
            int idx = q * 512 + tid;
            int r = idx >> 7, k = idx & 127;
            sATs[r * 132 + k] = ew2[l * 16384 + (r8 * 8 + r) * 128 + k];
        }
        __syncthreads();
        float d[4] = {0.f, 0.f, 0.f, 0.f};
        gemm_t(sATs, nw1 + l * 32768 + 16384, g, tg, c0, d);
        *(float2*)(g_Wc[l] + (r8 * 8 + g) * 128 + col) = make_float2(d[0], d[1]);
    } else if (rb == 48) {
        if (tid < 384) {
            int l = tid >> 7, c = tid & 127;
            const float* e2 = eb2 + l * 128;
            const float* W = nw1 + l * 32768 + 16384 + c;
            float s = 0.f;
#pragma unroll 8
            for (int m = 0; m < 128; m++) s = fmaf(e2[m], W[m * 128], s);
            g_cb[l][c] = s;
        }
    }
    bar_arrive(0, tid, sBarT);   // leading sync orders Wc-gemm sATs reads vs overwrite

    // ---- CTA-local setup, overlapped with other CTAs' Wc work ----
#pragma unroll
    for (int q = 0; q < 2; q++) {
        int idx = q * 512 + tid;
        int r = idx >> 7, k = idx & 127;
        float v = nf[rb * 1024 + idx];
        sX[idx] = v;
        sATs[r * 132 + k] = v;
    }
    const float* adjb = adj + (size_t)(b * 256 + il0) * 256;
#pragma unroll
    for (int e = 0; e < 4; e++) {
        int idx = e * 512 + tid;
        int r = idx >> 8, j = idx & 255;
        float v = adjb[r * 256 + j];
        *(float2*)(sAdj2 + j * 16 + 2 * r) = make_float2(v, v);
    }
    if (w < 8) {
        float s = 0.f;
        const float* row = adjb + w * 256;
#pragma unroll
        for (int j = lane; j < 256; j += 32) s += row[j];
#pragma unroll
        for (int o = 16; o; o >>= 1) s += __shfl_xor_sync(~0u, s, o);
        if (!lane) s_rs[w] = s;
    }
    bar_wait(0, tid, sBarT);   // orders sATs/sAdj2/sX init before layer 0

    // ================= layers =================
    for (int l = 0; l < L_; l++) {
        float* Pbuf = g_P[l & 1];
        const float* ew1l = ew1 + l * 32768;

        // ---- Pj = x @ ew1b -> global (stcg), then ARRIVE ----
        {
            float d[4] = {0.f, 0.f, 0.f, 0.f};
            gemm_t(sATs, ew1l + 16384, g, tg, c0, d);
            __stcg((u64*)(Pbuf + (rb * 8 + g) * 128 + col), pk(d[0], d[1]));
        }
        bar_arrive(1 + l, tid, sBarT);             // Pj published

        // ---- Pi = x @ ew1a + eb1 ; Pn = x @ nw1a + nb1 (hidden behind barrier) ----
        {
            float d[4] = {0.f, 0.f, 0.f, 0.f};
            gemm_t(sATs, ew1l, g, tg, c0, d);
            float2 be = *(const float2*)(eb1 + l * 128 + col);
            *(float2*)(sPi + g * 132 + col) = make_float2(d[0] + be.x, d[1] + be.y);
        }
        {
            float d[4] = {0.f, 0.f, 0.f, 0.f};
            gemm_t(sATs, nw1 + l * 32768, g, tg, c0, d);
            float2 bn = *(const float2*)(nb1 + l * 128 + col);
            *(float2*)(sPn + g * 132 + col) = make_float2(d[0] + bn.x, d[1] + bn.y);
        }
        bar_wait(1 + l, tid, sBarT);   // all Pj visible; sPi/sPn complete

        // ---- agg: direct LDG.cg from Pbuf, fp32 f32x2 math ----
        {
            u64 xi[4][2], aacc[4][2] = {};
#pragma unroll
            for (int q = 0; q < 4; q++) {
                ulonglong2 v = *(const ulonglong2*)(sPi + (ig * 4 + q) * 132 + lane * 4);
                xi[q][0] = v.x; xi[q][1] = v.y;
            }
            agg_ldg(Pbuf + b * 32768, sAdj2, xi, aacc, lane, ig, jq);
            float* o = sPart + jq * 1024 + ig * 4 * 128 + lane * 4;
#pragma unroll
            for (int q = 0; q < 4; q++) {
                float v0, v1, v2, v3;
                upk(aacc[q][0], v0, v1); upk(aacc[q][1], v2, v3);
                *(float4*)(o + q * 128) = make_float4(v0, v1, v2, v3);
            }
        }
        __syncthreads();
        {   // reduce agg partials -> plain sATs (stride 132)
            *(u64*)(sATs + pr * 132 + pcc) = reduce8_2(sPart, pf0);
        }
        __syncthreads();

        // ---- nh = relu(Pn + agg@Wc + rs*cb) -> sNTs ----
        {
            float d[4] = {0.f, 0.f, 0.f, 0.f};
            gemm_t(sATs, g_Wc[l], g, tg, c0, d);
            float2 pn = *(const float2*)(sPn + g * 132 + col);
            float2 cb = *(const float2*)(g_cb[l] + col);
            float rs = s_rs[g];
            float v0 = fmaxf(fmaf(rs, cb.x, d[0] + pn.x), 0.f);
            float v1 = fmaxf(fmaf(rs, cb.y, d[1] + pn.y), 0.f);
            *(float2*)(sNTs + g * 132 + col) = make_float2(v0, v1);
        }
        __syncthreads();

        // ---- x += nh @ nw2 + nb2 (fused: writes sX, next layer's sATs, x) ----
        {
            float d[4] = {0.f, 0.f, 0.f, 0.f};
            gemm_t(sNTs, nw2 + l * 16384, g, tg, c0, d);
            float2 bb = *(const float2*)(nb2 + l * 128 + col);
            float2 xv = *(const float2*)(sX + f0x);
            float v0 = xv.x + d[0] + bb.x;
            float v1 = xv.y + d[1] + bb.y;
            *(float2*)(sX + f0x) = make_float2(v0, v1);
            *(float2*)(sATs + g * 132 + col) = make_float2(v0, v1);
            if (l == L_ - 1) *(u64*)(x + rb * 1024 + f0x) = pk(v0, v1);
        }
        __syncthreads();   // sATs/sX stable before next layer
    }
}

// ---------------- launch ----------------
extern "C" void kernel_launch(void* const* d_in, const int* in_sizes, int n_in,
                              void* d_out, int out_size) {
    const float* nf  = (const float*)d_in[0];
    const float* adj = (const float*)d_in[1];
    const float* ew1 = (const float*)d_in[2];
    const float* eb1 = (const float*)d_in[3];
    const float* ew2 = (const float*)d_in[4];
    const float* eb2 = (const float*)d_in[5];
    const float* nw1 = (const float*)d_in[6];
    const float* nb1 = (const float*)d_in[7];
    const float* nw2 = (const float*)d_in[8];
    const float* nb2 = (const float*)d_in[9];
    float* x = (float*)d_out;

    const int SMEM = SMEM_FLOATS * 4;   // 70192 B
    cudaFuncSetAttribute(k_main, cudaFuncAttributeMaxDynamicSharedMemorySize, SMEM);
    k_main<<<NB, NT, SMEM>>>(x, nf, adj, ew1, eb1, ew2, eb2, nw1, nb1, nw2, nb2);
}

// round 17
// speedup vs baseline: 1.0412x; 1.0412x over previous
#include <cuda_runtime.h>
#include <cstdint>

typedef unsigned long long u64;
#define DEV static __device__ __forceinline__

static constexpr int L_ = 3;
static constexpr int NB = 128;   // 128 CTAs, 8 rows each
static constexpr int NT = 512;   // 16 warps

// ---------------- device globals ----------------
__device__ float g_P[2][1024 * 128];   // double-buffered Pj
__device__ float g_Wc[L_][128 * 128];  // ew2 @ nw1b
__device__ float g_cb[L_][128];        // eb2 @ nw1b
__device__ unsigned g_bar[4];          // monotonic barrier counters (replay-safe)

// ---------------- f32x2 helpers ----------------
DEV u64 pk(float lo, float hi) {
    u64 r; asm("mov.b64 %0,{%1,%2};" : "=l"(r) : "f"(lo), "f"(hi)); return r;
}
DEV void upk(u64 v, float& lo, float& hi) {
    asm("mov.b64 {%0,%1},%2;" : "=f"(lo), "=f"(hi) : "l"(v));
}
DEV u64 add2(u64 a, u64 b) {
    u64 r; asm("add.rn.f32x2 %0,%1,%2;" : "=l"(r) : "l"(a), "l"(b)); return r;
}
DEV u64 fma2(u64 a, u64 b, u64 c) {
    u64 r; asm("fma.rn.f32x2 %0,%1,%2,%3;" : "=l"(r) : "l"(a), "l"(b), "l"(c)); return r;
}
DEV u64 relu2(u64 v) {
    float lo, hi; upk(v, lo, hi);
    return pk(fmaxf(lo, 0.f), fmaxf(hi, 0.f));
}

// ---------------- split grid barrier (monotonic counters; replay-safe) ----------------
DEV unsigned ld_acq(const unsigned* p) {
    unsigned v;
    asm volatile("ld.acquire.gpu.global.u32 %0,[%1];" : "=r"(v) : "l"(p) : "memory");
    return v;
}
DEV void bar_arrive(int bidx, int tid, unsigned* sT) {
    __syncthreads();
    if (tid == 0) {
        __threadfence();
        unsigned t = atomicAdd(&g_bar[bidx], 1u);
        *sT = (t / (unsigned)NB + 1u) * (unsigned)NB;
    }
}
DEV void bar_wait(int bidx, int tid, unsigned* sT) {
    __syncthreads();
    if (tid == 0) {
        unsigned target = *sT;
        while (ld_acq(&g_bar[bidx]) < target) { __nanosleep(64); }
        __threadfence();
    }
    __syncthreads();
}

// ---------------- r=4 k-split-8 GEMM, W direct from global via __ldg --------------
// warp = (rg = w&1, kq = w>>1 of 8, 16 k each), lane = 4 cols.
// dup'd A layout: ATs[k*20 + 2r] = ATs[k*20+2r+1] = A[r][k]
DEV void gemm_g(const float* __restrict__ ATs, const float* __restrict__ W,
                int lane, int rg, int kq, u64 acc[4][2]) {
    const float* ap = ATs + kq * 16 * 20 + rg * 8;
    const float* wp = W + kq * 16 * 128 + lane * 4;
#pragma unroll
    for (int k = 0; k < 16; k++) {
        ulonglong2 wv = __ldg((const ulonglong2*)(wp + k * 128));
        ulonglong2 a01 = *(const ulonglong2*)(ap + k * 20);
        ulonglong2 a23 = *(const ulonglong2*)(ap + k * 20 + 4);
        acc[0][0] = fma2(a01.x, wv.x, acc[0][0]);
        acc[0][1] = fma2(a01.x, wv.y, acc[0][1]);
        acc[1][0] = fma2(a01.y, wv.x, acc[1][0]);
        acc[1][1] = fma2(a01.y, wv.y, acc[1][1]);
        acc[2][0] = fma2(a23.x, wv.x, acc[2][0]);
        acc[2][1] = fma2(a23.x, wv.y, acc[2][1]);
        acc[3][0] = fma2(a23.y, wv.x, acc[3][0]);
        acc[3][1] = fma2(a23.y, wv.y, acc[3][1]);
    }
}

// ---------------- merged 8x256 GEMM: warp=(cg2,rg2,kq4), 32 k each, W via __ldg ----
DEV void gemm_m_g(const float* __restrict__ ATs, const float* __restrict__ W,
                  int lane, int rg, int kq, u64 acc[4][2]) {
    const float* ap = ATs + kq * 32 * 20 + rg * 8;
    const float* wp = W + kq * 32 * 128 + lane * 4;
#pragma unroll 16
    for (int k = 0; k < 32; k++) {
        ulonglong2 wv = __ldg((const ulonglong2*)(wp + k * 128));
        ulonglong2 a01 = *(const ulonglong2*)(ap + k * 20);
        ulonglong2 a23 = *(const ulonglong2*)(ap + k * 20 + 4);
        acc[0][0] = fma2(a01.x, wv.x, acc[0][0]);
        acc[0][1] = fma2(a01.x, wv.y, acc[0][1]);
        acc[1][0] = fma2(a01.y, wv.x, acc[1][0]);
        acc[1][1] = fma2(a01.y, wv.y, acc[1][1]);
        acc[2][0] = fma2(a23.x, wv.x, acc[2][0]);
        acc[2][1] = fma2(a23.x, wv.y, acc[2][1]);
        acc[3][0] = fma2(a23.y, wv.x, acc[3][0]);
        acc[3][1] = fma2(a23.y, wv.y, acc[3][1]);
    }
}

DEV void store_part8(float* sPart, const u64 acc[4][2], int lane, int rg, int kq) {
    float* o = sPart + kq * 1024 + rg * 4 * 128 + lane * 4;
#pragma unroll
    for (int r = 0; r < 4; r++) {
        ulonglong2 st; st.x = acc[r][0]; st.y = acc[r][1];
        *(ulonglong2*)(o + r * 128) = st;
    }
}

// u64 pair-reduce: f0 = even float offset of the pair; partial stride 1024
DEV u64 reduce8_2(const float* __restrict__ sPart, int f0) {
    u64 p0 = *(const u64*)(sPart + f0);
    u64 p1 = *(const u64*)(sPart + f0 + 1024);
    u64 p2 = *(const u64*)(sPart + f0 + 2048);
    u64 p3 = *(const u64*)(sPart + f0 + 3072);
    u64 p4 = *(const u64*)(sPart + f0 + 4096);
    u64 p5 = *(const u64*)(sPart + f0 + 5120);
    u64 p6 = *(const u64*)(sPart + f0 + 6144);
    u64 p7 = *(const u64*)(sPart + f0 + 7168);
    return add2(add2(add2(p0, p1), add2(p2, p3)), add2(add2(p4, p5), add2(p6, p7)));
}

// u64 pair-reduce over 4 partials with stride 2048 (merged GEMM)
DEV u64 reduce4_2(const float* __restrict__ sPart, int f0) {
    u64 p0 = *(const u64*)(sPart + f0);
    u64 p1 = *(const u64*)(sPart + f0 + 2048);
    u64 p2 = *(const u64*)(sPart + f0 + 4096);
    u64 p3 = *(const u64*)(sPart + f0 + 6144);
    return add2(add2(p0, p1), add2(p2, p3));
}

// ---------------- agg via direct LDG.cg: warp=(ig2,jq8), 4i x 4d, 32 j ----------
DEV void agg_ldg(const float* __restrict__ Pjb, const float* __restrict__ sAdj2,
                 const u64 xi[4][2], u64 acc[4][2], int lane, int ig, int jq) {
    const float* pj = Pjb + jq * 32 * 128 + lane * 4;
    const float* ad = sAdj2 + jq * 32 * 16 + ig * 8;
#pragma unroll 8
    for (int jj = 0; jj < 32; jj++) {
        ulonglong2 xj = __ldcg((const ulonglong2*)(pj + jj * 128));
        ulonglong2 a01 = *(const ulonglong2*)(ad + jj * 16);
        ulonglong2 a23 = *(const ulonglong2*)(ad + jj * 16 + 4);
        u64 t;
        t = relu2(add2(xi[0][0], xj.x)); acc[0][0] = fma2(t, a01.x, acc[0][0]);
        t = relu2(add2(xi[0][1], xj.y)); acc[0][1] = fma2(t, a01.x, acc[0][1]);
        t = relu2(add2(xi[1][0], xj.x)); acc[1][0] = fma2(t, a01.y, acc[1][0]);
        t = relu2(add2(xi[1][1], xj.y)); acc[1][1] = fma2(t, a01.y, acc[1][1]);
        t = relu2(add2(xi[2][0], xj.x)); acc[2][0] = fma2(t, a23.x, acc[2][0]);
        t = relu2(add2(xi[2][1], xj.y)); acc[2][1] = fma2(t, a23.x, acc[2][1]);
        t = relu2(add2(xi[3][0], xj.x)); acc[3][0] = fma2(t, a23.y, acc[3][0]);
        t = relu2(add2(xi[3][1], xj.y)); acc[3][1] = fma2(t, a23.y, acc[3][1]);
    }
}

// ---------------- smem layout (floats) ----------------
// sPart 0 (8192) | sATs 8192 (2560) | sNTs 10752 (2560) | sPi 13312 (1024)
// sPn 14336 (1024) | sAdj2 15360 (4096) | s_rs 19456 (8) | sX 19464 (1024)
// sBarT 20488 (1)
static constexpr int SMEM_FLOATS = 20489;   // 81956 B

__global__ void __launch_bounds__(NT, 1) k_main(
    float* __restrict__ x, const float* __restrict__ nf, const float* __restrict__ adj,
    const float* __restrict__ ew1, const float* __restrict__ eb1,
    const float* __restrict__ ew2, const float* __restrict__ eb2,
    const float* __restrict__ nw1, const float* __restrict__ nb1,
    const float* __restrict__ nw2, const float* __restrict__ nb2) {
    extern __shared__ float sm[];
    float* sPart = sm;
    float* sATs = sm + 8192;
    float* sNTs = sm + 10752;
    float* sPi = sm + 13312;
    float* sPn = sm + 14336;
    float* sAdj2 = sm + 15360;
    float* s_rs = sm + 19456;
    float* sX = sm + 19464;
    unsigned* sBarT = (unsigned*)(sm + 20488);

    int tid = threadIdx.x, lane = tid & 31, w = tid >> 5;
    int rb = blockIdx.x;        // rows rb*8 .. rb*8+7
    int b = rb >> 5;            // batch
    int il0 = (rb & 31) * 8;    // local i base in batch
    int rg = w & 1, kq = w >> 1;              // r4k8 roles
    int mcg = w & 1, mrg = (w >> 1) & 1, mkq = w >> 2;   // merged-GEMM roles
    int ig = w & 1, jq = w >> 1;              // agg roles
    int pf0 = 2 * tid;                        // pair-epilogue float offset
    int pr = tid >> 6;                        // pair-epilogue row (pf0 >> 7)
    int pc = pf0 & 127;                       // pair-epilogue col0

    // ================= setup: produce Wc/cb, arrive, local setup, wait ==========
    if (rb < 48) {   // Wc[l] = ew2[l] @ nw1b[l]
        int l = rb / 16, r8 = rb % 16;
#pragma unroll
        for (int q = 0; q < 2; q++) {
            int idx = q * 512 + tid;
            int r = idx >> 7, k = idx & 127;
            float v = ew2[l * 16384 + (r8 * 8 + r) * 128 + k];
            *(float2*)(sATs + k * 20 + 2 * r) = make_float2(v, v);
        }
        __syncthreads();
        u64 acc[4][2] = {};
        gemm_g(sATs, nw1 + l * 32768 + 16384, lane, rg, kq, acc);
        store_part8(sPart, acc, lane, rg, kq);
        __syncthreads();
        *(u64*)(g_Wc[l] + (r8 * 8 + pr) * 128 + pc) = reduce8_2(sPart, pf0);
    } else if (rb == 48) {
        if (tid < 384) {
            int l = tid >> 7, c = tid & 127;
            const float* e2 = eb2 + l * 128;
            const float* W = nw1 + l * 32768 + 16384 + c;
            float s = 0.f;
#pragma unroll 8
            for (int m = 0; m < 128; m++) s = fmaf(e2[m], W[m * 128], s);
            g_cb[l][c] = s;
        }
    }
    bar_arrive(0, tid, sBarT);

    // ---- CTA-local setup, overlapped with other CTAs' Wc work ----
#pragma unroll
    for (int q = 0; q < 2; q++) sX[q * 512 + tid] = nf[rb * 1024 + q * 512 + tid];
    const float* adjb = adj + (size_t)(b * 256 + il0) * 256;
#pragma unroll
    for (int e = 0; e < 4; e++) {
        int idx = e * 512 + tid;
        int r = idx >> 8, j = idx & 255;
        float v = adjb[r * 256 + j];
        *(float2*)(sAdj2 + j * 16 + 2 * r) = make_float2(v, v);
    }
    if (w < 8) {
        float s = 0.f;
        const float* row = adjb + w * 256;
#pragma unroll
        for (int j = lane; j < 256; j += 32) s += row[j];
#pragma unroll
        for (int o = 16; o; o >>= 1) s += __shfl_xor_sync(~0u, s, o);
        if (!lane) s_rs[w] = s;
    }
    // pre-loop: dup'd sATs from sX (own values)
#pragma unroll
    for (int q = 0; q < 2; q++) {
        int idx = q * 512 + tid;
        int r = idx >> 7, k = idx & 127;
        float v = sX[idx];
        *(float2*)(sATs + k * 20 + 2 * r) = make_float2(v, v);
    }
    bar_wait(0, tid, sBarT);   // also orders sATs init before layer-0 GEMM reads

    // ================= layers =================
    for (int l = 0; l < L_; l++) {
        float* Pbuf = g_P[l & 1];
        const float* ew1l = ew1 + l * 32768;

        // ---- Pj = x @ ew1b -> global (stcg), then ARRIVE ----
        {
            u64 acc[4][2] = {};
            gemm_g(sATs, ew1l + 16384, lane, rg, kq, acc);
            store_part8(sPart, acc, lane, rg, kq);
            __syncthreads();
            __stcg((u64*)(Pbuf + (rb * 8 + pr) * 128 + pc), reduce8_2(sPart, pf0));
        }
        bar_arrive(1 + l, tid, sBarT);             // Pj published (sync inside)

        // ---- merged: [Pi|Pn] = x @ [ew1a | nw1a] + [eb1|nb1] (hidden behind barrier) ----
        {
            u64 acc[4][2] = {};
            gemm_m_g(sATs, mcg ? (nw1 + l * 32768) : ew1l, lane, mrg, mkq, acc);
            {   // store to sPart[kq][8r][256c]
                float* o = sPart + mkq * 2048 + mrg * 4 * 256 + mcg * 128 + lane * 4;
#pragma unroll
                for (int r = 0; r < 4; r++) {
                    ulonglong2 st; st.x = acc[r][0]; st.y = acc[r][1];
                    *(ulonglong2*)(o + r * 256) = st;
                }
            }
            __syncthreads();
#pragma unroll
            for (int q = 0; q < 2; q++) {
                int i = q * 512 + tid;             // pair index 0..1023
                int f0 = 2 * i;
                int r = f0 >> 8, c = f0 & 255;
                u64 v = reduce4_2(sPart, f0);
                if (c < 128) {
                    u64 bb = *(const u64*)(eb1 + l * 128 + c);
                    *(u64*)(sPi + r * 128 + c) = add2(v, bb);
                } else {
                    int c2 = c - 128;
                    u64 bb = *(const u64*)(nb1 + l * 128 + c2);
                    *(u64*)(sPn + r * 128 + c2) = add2(v, bb);
                }
            }
        }
        bar_wait(1 + l, tid, sBarT);   // all Pj visible; sPi/sPn complete

        // ---- agg: direct LDG.cg from Pbuf (R14 proven form) ----
        {
            u64 xi[4][2], aacc[4][2] = {};
#pragma unroll
            for (int q = 0; q < 4; q++) {
                ulonglong2 v = *(const ulonglong2*)(sPi + (ig * 4 + q) * 128 + lane * 4);
                xi[q][0] = v.x; xi[q][1] = v.y;
            }
            agg_ldg(Pbuf + b * 32768, sAdj2, xi, aacc, lane, ig, jq);
            float* o = sPart + jq * 1024 + ig * 4 * 128 + lane * 4;
#pragma unroll
            for (int q = 0; q < 4; q++) {
                ulonglong2 st; st.x = aacc[q][0]; st.y = aacc[q][1];
                *(ulonglong2*)(o + q * 128) = st;
            }
        }
        __syncthreads();
        {   // reduce agg -> dup'd sATs (u64 pairs, single pass)
            u64 v = reduce8_2(sPart, pf0);
            float v0, v1; upk(v, v0, v1);
            *(float2*)(sATs + pc * 20 + 2 * pr) = make_float2(v0, v0);
            *(float2*)(sATs + (pc + 1) * 20 + 2 * pr) = make_float2(v1, v1);
        }
        __syncthreads();

        // ---- nh = relu(Pn + agg@Wc + rs*cb) (single-pass pair epilogue) ----
        {
            u64 acc[4][2] = {};
            gemm_g(sATs, g_Wc[l], lane, rg, kq, acc);
            store_part8(sPart, acc, lane, rg, kq);
            __syncthreads();
            u64 pn = *(const u64*)(sPn + pf0);
            u64 cbp = *(const u64*)(g_cb[l] + pc);
            float rs = s_rs[pr];
            u64 v = relu2(fma2(pk(rs, rs), cbp, add2(reduce8_2(sPart, pf0), pn)));
            float v0, v1; upk(v, v0, v1);
            *(float2*)(sNTs + pc * 20 + 2 * pr) = make_float2(v0, v0);
            *(float2*)(sNTs + (pc + 1) * 20 + 2 * pr) = make_float2(v1, v1);
            __syncthreads();
        }

        // ---- x += nh @ nw2 + nb2 (single-pass pair epilogue; fuses next sATs) ----
        {
            u64 acc[4][2] = {};
            gemm_g(sNTs, nw2 + l * 16384, lane, rg, kq, acc);
            store_part8(sPart, acc, lane, rg, kq);
            __syncthreads();
            u64 bb = *(const u64*)(nb2 + l * 128 + pc);
            u64 v = add2(*(const u64*)(sX + pf0), add2(reduce8_2(sPart, pf0), bb));
            *(u64*)(sX + pf0) = v;
            float v0, v1; upk(v, v0, v1);
            *(float2*)(sATs + pc * 20 + 2 * pr) = make_float2(v0, v0);
            *(float2*)(sATs + (pc + 1) * 20 + 2 * pr) = make_float2(v1, v1);
            if (l == L_ - 1) *(u64*)(x + rb * 1024 + pf0) = v;
            __syncthreads();   // sATs/sX/sPart stable before next layer
        }
    }
}

// ---------------- launch ----------------
extern "C" void kernel_launch(void* const* d_in, const int* in_sizes, int n_in,
                              void* d_out, int out_size) {
    const float* nf  = (const float*)d_in[0];
    const float* adj = (const float*)d_in[1];
    const float* ew1 = (const float*)d_in[2];
    const float* eb1 = (const float*)d_in[3];
    const float* ew2 = (const float*)d_in[4];
    const float* eb2 = (const float*)d_in[5];
    const float* nw1 = (const float*)d_in[6];
    const float* nb1 = (const float*)d_in[7];
    const float* nw2 = (const float*)d_in[8];
    const float* nb2 = (const float*)d_in[9];
    float* x = (float*)d_out;

    const int SMEM = SMEM_FLOATS * 4;   // 81956 B
    cudaFuncSetAttribute(k_main, cudaFuncAttributeMaxDynamicSharedMemorySize, SMEM);
    k_main<<<NB, NT, SMEM>>>(x, nf, adj, ew1, eb1, ew2, eb2, nw1, nb1, nw2, nb2);
}